// round 12
// baseline (speedup 1.0000x reference)
#include <cuda_runtime.h>
#include <cuda_bf16.h>
#include <cstdint>

// Problem: B=4, N=4096 (64x64), C=64, Cf=8
#define BATCH 4
#define NTOK  4096
#define CDIM  64
#define CF    8
#define BN    (BATCH * NTOK)
#define KT    64               // keys per tile
#define HTILE 32               // tiles per key-half (NTOK/2/KT)
#define QPC   64               // queries per CTA
#define HP    72               // hS pitch (elements) - conflict-free for ldmatrix
#define STG   4                // cp.async pipeline stages

// ---------------- scratch (no cudaMalloc allowed) ----------------
__device__ __nv_bfloat16 d_fb[BN * CF];              // keys    [B,N,8]
__device__ __nv_bfloat16 d_gb[BN * CF];              // queries [B,N,8]
__device__ __nv_bfloat16 d_htb[BATCH * CDIM * NTOK]; // values transposed [B,C,N]

#define MMA16816(d, a0, a1, a2, a3, b0, b1, c) \
    asm volatile("mma.sync.aligned.m16n8k16.row.col.f32.bf16.bf16.f32 " \
        "{%0,%1,%2,%3}, {%4,%5,%6,%7}, {%8,%9}, {%10,%11,%12,%13};" \
        : "=f"((d)[0]), "=f"((d)[1]), "=f"((d)[2]), "=f"((d)[3]) \
        : "r"(a0), "r"(a1), "r"(a2), "r"(a3), "r"(b0), "r"(b1), \
          "f"((c)[0]), "f"((c)[1]), "f"((c)[2]), "f"((c)[3]))

#define MMA1688(d, a0, a1, b0, c) \
    asm volatile("mma.sync.aligned.m16n8k8.row.col.f32.bf16.bf16.f32 " \
        "{%0,%1,%2,%3}, {%4,%5}, {%6}, {%7,%8,%9,%10};" \
        : "=f"((d)[0]), "=f"((d)[1]), "=f"((d)[2]), "=f"((d)[3]) \
        : "r"(a0), "r"(a1), "r"(b0), \
          "f"((c)[0]), "f"((c)[1]), "f"((c)[2]), "f"((c)[3]))

#define CVT_BF16X2(res, lo, hi) \
    asm("cvt.rn.bf16x2.f32 %0, %1, %2;" : "=r"(res) : "f"(hi), "f"(lo))

__device__ __forceinline__ void cp16(void* dst, const void* src) {
    const uint32_t d = (uint32_t)__cvta_generic_to_shared(dst);
    asm volatile("cp.async.cg.shared.global [%0], [%1], 16;" :: "r"(d), "l"(src));
}
#define CP_COMMIT() asm volatile("cp.async.commit_group;" ::: "memory")
#define CP_WAIT2()  asm volatile("cp.async.wait_group 2;" ::: "memory")

__device__ __forceinline__ void ldmat4(uint32_t& r0, uint32_t& r1, uint32_t& r2,
                                       uint32_t& r3, const void* p) {
    const uint32_t a = (uint32_t)__cvta_generic_to_shared(p);
    asm volatile("ldmatrix.sync.aligned.m8n8.x4.shared.b16 {%0,%1,%2,%3}, [%4];"
                 : "=r"(r0), "=r"(r1), "=r"(r2), "=r"(r3) : "r"(a));
}

// ---------------- kernel 1: fused projections -> bf16 ----------------
__global__ void proj_kernel(const float* __restrict__ x,
                            const float* __restrict__ w_f, const float* __restrict__ b_f,
                            const float* __restrict__ w_g, const float* __restrict__ b_g,
                            const float* __restrict__ w_h, const float* __restrict__ b_h) {
    __shared__ float wf_s[CDIM * CF];
    __shared__ float wg_s[CDIM * CF];
    __shared__ float wh_s[CDIM * CDIM];
    __shared__ float bf_s[CF], bg_s[CF], bh_s[CDIM];
    __shared__ float xs[32][CDIM];
    __shared__ float hs[CDIM][33];

    const int tid = threadIdx.x;
    for (int i = tid; i < CDIM * CF; i += 256) { wf_s[i] = w_f[i]; wg_s[i] = w_g[i]; }
    for (int i = tid; i < CDIM * CDIM; i += 256) wh_s[i] = w_h[i];
    if (tid < CF)   { bf_s[tid] = b_f[tid]; bg_s[tid] = b_g[tid]; }
    if (tid < CDIM) bh_s[tid] = b_h[tid];

    const int row0 = blockIdx.x * 32;
    for (int i = tid; i < 32 * CDIM; i += 256)
        xs[i / CDIM][i % CDIM] = x[(row0 + i / CDIM) * CDIM + (i % CDIM)];
    __syncthreads();

    for (int idx = tid; idx < 32 * 80; idx += 256) {
        const int r = idx / 80, c = idx % 80;
        const float* w; float bias; int stride;
        if (c < 8)       { w = wf_s + c;        bias = bf_s[c];      stride = CF;   }
        else if (c < 16) { w = wg_s + (c - 8);  bias = bg_s[c - 8];  stride = CF;   }
        else             { w = wh_s + (c - 16); bias = bh_s[c - 16]; stride = CDIM; }
        float acc = bias;
        #pragma unroll
        for (int k = 0; k < CDIM; k++) acc += xs[r][k] * w[k * stride];
        const int row = row0 + r;
        if (c < 8)       d_fb[row * CF + c] = __float2bfloat16(acc);
        else if (c < 16) d_gb[row * CF + (c - 8)] = __float2bfloat16(acc);
        else             hs[c - 16][r] = acc;
    }
    __syncthreads();

    {
        const int b  = row0 >> 12;
        const int n0 = row0 & (NTOK - 1);
        const int ch = tid >> 2;
        const int part = (tid & 3) * 8;
        __nv_bfloat16 v[8];
        #pragma unroll
        for (int j = 0; j < 8; j++) v[j] = __float2bfloat16(hs[ch][part + j]);
        *reinterpret_cast<uint4*>(d_htb + ((size_t)b * CDIM + ch) * NTOK + n0 + part) =
            *reinterpret_cast<const uint4*>(v);
    }
}

// ---------------- kernel 2: HMMA flash attention, in-CTA split-K ------
// 8 warps: warps 0-3 handle keys [0,2048), warps 4-7 keys [2048,4096),
// same 64 queries. Partials combined through smem. Grid (64,4)=256 CTAs,
// 16 warps/SM. 4-stage cp.async ring per half, ldmatrix.x4 B-fragments.
__global__ __launch_bounds__(256, 2)
void attn_kernel(const float* __restrict__ x,
                 const float* __restrict__ gamma,
                 float* __restrict__ out) {
    __shared__ __nv_bfloat16 fS[2][STG][KT * CF];    // [half][stage], 1 KB each
    __shared__ __nv_bfloat16 hS[2][STG][CDIM * HP];  // [half][stage], 9 KB each

    const int tid   = threadIdx.x;
    const int warp  = tid >> 5;
    const int half  = warp >> 2;        // key-half 0/1
    const int wq    = warp & 3;         // q-tile within CTA
    const int htid  = tid & 127;        // thread id within half
    const int lane  = tid & 31;
    const int gid   = lane >> 2;
    const int tig   = lane & 3;
    const int mat   = lane >> 3;
    const int mrow  = lane & 7;

    const int b    = blockIdx.y;
    const int q0   = blockIdx.x * QPC + wq * 16;
    const int row0 = b * NTOK + q0;
    const int k0   = half * (NTOK / 2);    // key offset for this half

    const int f_off = (mat * 8 + mrow) * CF;
    const int h_off = ((mat >> 1) * 8 + mrow) * HP + (mat & 1) * 8;

    const uint32_t ga0 = *reinterpret_cast<const uint32_t*>(d_gb + (row0 + gid) * CF + tig * 2);
    const uint32_t ga1 = *reinterpret_cast<const uint32_t*>(d_gb + (row0 + 8 + gid) * CF + tig * 2);

    float O[8][4];
    #pragma unroll
    for (int n = 0; n < 8; n++)
        #pragma unroll
        for (int j = 0; j < 4; j++) O[n][j] = 0.0f;
    float l0 = 0.0f, l1 = 0.0f;
    const float zc[4] = {0.0f, 0.0f, 0.0f, 0.0f};

    auto load_tile = [&](int t) {
        const int buf = t & (STG - 1);
        if (htid < 64)
            cp16(&fS[half][buf][htid * CF],
                 d_fb + (size_t)(b * NTOK + k0 + t * KT + htid) * CF);
        const __nv_bfloat16* hsrc = d_htb + (size_t)b * CDIM * NTOK + k0 + t * KT;
        #pragma unroll
        for (int k2 = 0; k2 < 4; k2++) {
            const int i  = htid + k2 * 128;
            const int ch = i >> 3, ck = i & 7;
            cp16(&hS[half][buf][ch * HP + ck * 8], hsrc + (size_t)ch * NTOK + ck * 8);
        }
    };

    load_tile(0); CP_COMMIT();
    load_tile(1); CP_COMMIT();
    load_tile(2); CP_COMMIT();

    for (int t = 0; t < HTILE; t++) {
        CP_WAIT2();
        __syncthreads();
        if (t + 3 < HTILE) load_tile(t + 3);
        CP_COMMIT();

        const int buf = t & (STG - 1);

        // --- QK ---
        float S[8][4];
        {
            uint32_t fb[8];
            ldmat4(fb[0], fb[1], fb[2], fb[3], &fS[half][buf][f_off]);
            ldmat4(fb[4], fb[5], fb[6], fb[7], &fS[half][buf][f_off + 32 * CF]);
            #pragma unroll
            for (int n = 0; n < 8; n++) MMA1688(S[n], ga0, ga1, fb[n], zc);
        }

        // --- exp + partial row sums + pack P ---
        uint32_t P[8][2];
        #pragma unroll
        for (int n = 0; n < 8; n++) {
            const float e0 = __expf(S[n][0]);
            const float e1 = __expf(S[n][1]);
            const float e2 = __expf(S[n][2]);
            const float e3 = __expf(S[n][3]);
            l0 += e0 + e1;
            l1 += e2 + e3;
            CVT_BF16X2(P[n][0], e0, e1);
            CVT_BF16X2(P[n][1], e2, e3);
        }

        // --- PV ---
        #pragma unroll
        for (int kk = 0; kk < 4; kk++) {
            const uint32_t a0 = P[2 * kk][0];
            const uint32_t a1 = P[2 * kk][1];
            const uint32_t a2 = P[2 * kk + 1][0];
            const uint32_t a3 = P[2 * kk + 1][1];
            #pragma unroll
            for (int np = 0; np < 4; np++) {
                uint32_t b0, b1, b2, b3;
                ldmat4(b0, b1, b2, b3, &hS[half][buf][h_off + np * 16 * HP + kk * 16]);
                MMA16816(O[2 * np],     a0, a1, a2, a3, b0, b1, O[2 * np]);
                MMA16816(O[2 * np + 1], a0, a1, a2, a3, b2, b3, O[2 * np + 1]);
            }
        }
    }

    // ---- combine halves through smem (reuse pipeline buffers) ----
    __syncthreads();   // everyone done with pipeline smem
    float* cb = reinterpret_cast<float*>(&hS[0][0][0]);   // 17 KB needed, 36 KB avail
    const int slot = (wq * 32 + lane) * 34;
    if (half == 1) {
        #pragma unroll
        for (int n = 0; n < 8; n++)
            #pragma unroll
            for (int j = 0; j < 4; j++) cb[slot + n * 4 + j] = O[n][j];
        cb[slot + 32] = l0;
        cb[slot + 33] = l1;
    }
    __syncthreads();
    if (half == 1) return;

    #pragma unroll
    for (int n = 0; n < 8; n++)
        #pragma unroll
        for (int j = 0; j < 4; j++) O[n][j] += cb[slot + n * 4 + j];
    l0 += cb[slot + 32];
    l1 += cb[slot + 33];

    l0 += __shfl_xor_sync(0xFFFFFFFF, l0, 1);
    l0 += __shfl_xor_sync(0xFFFFFFFF, l0, 2);
    l1 += __shfl_xor_sync(0xFFFFFFFF, l1, 1);
    l1 += __shfl_xor_sync(0xFFFFFFFF, l1, 2);

    const float gm   = gamma[0];
    const float inv0 = gm / l0;
    const float inv1 = gm / l1;

    const size_t base0 = (size_t)(row0 + gid) * CDIM;
    const size_t base1 = (size_t)(row0 + 8 + gid) * CDIM;
    #pragma unroll
    for (int n = 0; n < 8; n++) {
        const int ch = n * 8 + tig * 2;
        const float2 xv0 = *reinterpret_cast<const float2*>(x + base0 + ch);
        const float2 xv1 = *reinterpret_cast<const float2*>(x + base1 + ch);
        float2 o0, o1;
        o0.x = fmaf(inv0, O[n][0], xv0.x);
        o0.y = fmaf(inv0, O[n][1], xv0.y);
        o1.x = fmaf(inv1, O[n][2], xv1.x);
        o1.y = fmaf(inv1, O[n][3], xv1.y);
        *reinterpret_cast<float2*>(out + base0 + ch) = o0;
        *reinterpret_cast<float2*>(out + base1 + ch) = o1;
    }
}

// ---------------- launch ----------------
extern "C" void kernel_launch(void* const* d_in, const int* in_sizes, int n_in,
                              void* d_out, int out_size) {
    const float* x     = (const float*)d_in[0];
    const float* w_f   = (const float*)d_in[1];
    const float* b_f   = (const float*)d_in[2];
    const float* w_g   = (const float*)d_in[3];
    const float* b_g   = (const float*)d_in[4];
    const float* w_h   = (const float*)d_in[5];
    const float* b_h   = (const float*)d_in[6];
    const float* gamma = (const float*)d_in[7];
    float* out = (float*)d_out;

    proj_kernel<<<BN / 32, 256>>>(x, w_f, b_f, w_g, b_g, w_h, b_h);
    attn_kernel<<<dim3(NTOK / QPC, BATCH), 256>>>(x, gamma, out);
}

// round 13
// speedup vs baseline: 1.1279x; 1.1279x over previous
#include <cuda_runtime.h>
#include <cuda_bf16.h>
#include <cstdint>

// Problem: B=4, N=4096 (64x64), C=64, Cf=8
#define BATCH 4
#define NTOK  4096
#define CDIM  64
#define CF    8
#define BN    (BATCH * NTOK)
#define KT    64               // keys per tile
#define NTILE (NTOK / KT)      // 64
#define QPC   64               // queries per CTA (4 warps x 16)
#define HP    72               // hS pitch (elements) - conflict-free for ldmatrix
#define STG   4                // cp.async pipeline stages
#define NCTA  256              // total CTAs (all resident: >=4 CTAs/SM capacity)

// ---------------- scratch (no cudaMalloc allowed) ----------------
__device__ __nv_bfloat16 d_fb[BN * CF];              // keys    [B,N,8]
__device__ __nv_bfloat16 d_gb[BN * CF];              // queries [B,N,8]
__device__ __nv_bfloat16 d_htb[BATCH * CDIM * NTOK]; // values transposed [B,C,N]
__device__ unsigned int  d_bar = 0;                  // device-wide barrier ticket

#define MMA16816(d, a0, a1, a2, a3, b0, b1, c) \
    asm volatile("mma.sync.aligned.m16n8k16.row.col.f32.bf16.bf16.f32 " \
        "{%0,%1,%2,%3}, {%4,%5,%6,%7}, {%8,%9}, {%10,%11,%12,%13};" \
        : "=f"((d)[0]), "=f"((d)[1]), "=f"((d)[2]), "=f"((d)[3]) \
        : "r"(a0), "r"(a1), "r"(a2), "r"(a3), "r"(b0), "r"(b1), \
          "f"((c)[0]), "f"((c)[1]), "f"((c)[2]), "f"((c)[3]))

#define MMA1688(d, a0, a1, b0, c) \
    asm volatile("mma.sync.aligned.m16n8k8.row.col.f32.bf16.bf16.f32 " \
        "{%0,%1,%2,%3}, {%4,%5}, {%6}, {%7,%8,%9,%10};" \
        : "=f"((d)[0]), "=f"((d)[1]), "=f"((d)[2]), "=f"((d)[3]) \
        : "r"(a0), "r"(a1), "r"(b0), \
          "f"((c)[0]), "f"((c)[1]), "f"((c)[2]), "f"((c)[3]))

#define CVT_BF16X2(res, lo, hi) \
    asm("cvt.rn.bf16x2.f32 %0, %1, %2;" : "=r"(res) : "f"(hi), "f"(lo))

__device__ __forceinline__ void cp16(void* dst, const void* src) {
    const uint32_t d = (uint32_t)__cvta_generic_to_shared(dst);
    asm volatile("cp.async.cg.shared.global [%0], [%1], 16;" :: "r"(d), "l"(src));
}
#define CP_COMMIT() asm volatile("cp.async.commit_group;" ::: "memory")
#define CP_WAIT2()  asm volatile("cp.async.wait_group 2;" ::: "memory")

__device__ __forceinline__ void ldmat4(uint32_t& r0, uint32_t& r1, uint32_t& r2,
                                       uint32_t& r3, const void* p) {
    const uint32_t a = (uint32_t)__cvta_generic_to_shared(p);
    asm volatile("ldmatrix.sync.aligned.m8n8.x4.shared.b16 {%0,%1,%2,%3}, [%4];"
                 : "=r"(r0), "=r"(r1), "=r"(r2), "=r"(r3) : "r"(a));
}

// shared-memory overlay (40960 bytes)
//  attn: fS stage s @ s*1024 (4x1KB), hS stage s @ 4096 + s*9216 (4x9KB)
//  proj: wfT@0 [8][68], wgT@2176, whT@4352 [64][68], biases@21760,
//        xs@22080 [32][68], hs@30784 [64][33]
#define SM_BYTES 40960
#define P_WFT 0
#define P_WGT 2176
#define P_WHT 4352
#define P_BF  21760
#define P_BG  21792
#define P_BH  21824
#define P_XS  22080
#define P_HS  30784

__global__ __launch_bounds__(128, 2)
void fused_kernel(const float* __restrict__ x,
                  const float* __restrict__ w_f, const float* __restrict__ b_f,
                  const float* __restrict__ w_g, const float* __restrict__ b_g,
                  const float* __restrict__ w_h, const float* __restrict__ b_h,
                  const float* __restrict__ gamma,
                  float* __restrict__ out) {
    __shared__ __align__(16) char smraw[SM_BYTES];

    const int tid = threadIdx.x;

    // ================= phase 1: projections =================
    {
        float* wfT = (float*)(smraw + P_WFT);
        float* wgT = (float*)(smraw + P_WGT);
        float* whT = (float*)(smraw + P_WHT);
        float* bfs = (float*)(smraw + P_BF);
        float* bgs = (float*)(smraw + P_BG);
        float* bhs = (float*)(smraw + P_BH);
        float* xs  = (float*)(smraw + P_XS);
        float* hs  = (float*)(smraw + P_HS);

        // weights transposed: wT[c][k], pitch 68
        for (int i = tid; i < CDIM * CF; i += 128) {
            const int k = i >> 3, c = i & 7;
            wfT[c * 68 + k] = w_f[i];
            wgT[c * 68 + k] = w_g[i];
        }
        for (int i = tid; i < CDIM * CDIM; i += 128) {
            const int k = i >> 6, c = i & 63;
            whT[c * 68 + k] = w_h[i];
        }
        if (tid < CF)   { bfs[tid] = b_f[tid]; bgs[tid] = b_g[tid]; }
        if (tid < CDIM) bhs[tid] = b_h[tid];

        const int cta  = blockIdx.y * gridDim.x + blockIdx.x;   // 0..255
        const int rowb = cta * 64;

        #pragma unroll 1
        for (int c2 = 0; c2 < 2; c2++) {
            const int r0 = rowb + c2 * 32;
            __syncthreads();
            for (int i = tid; i < 32 * CDIM; i += 128)
                xs[(i >> 6) * 68 + (i & 63)] = x[(size_t)(r0 + (i >> 6)) * CDIM + (i & 63)];
            __syncthreads();

            for (int idx = tid; idx < 32 * 80; idx += 128) {
                const int r = idx / 80, c = idx % 80;
                const float4* wv; float bias;
                if (c < 8)       { wv = (const float4*)(wfT + c * 68);        bias = bfs[c];      }
                else if (c < 16) { wv = (const float4*)(wgT + (c - 8) * 68);  bias = bgs[c - 8];  }
                else             { wv = (const float4*)(whT + (c - 16) * 68); bias = bhs[c - 16]; }
                const float4* xv = (const float4*)(xs + r * 68);
                float acc = bias;
                #pragma unroll
                for (int k = 0; k < 16; k++) {
                    const float4 a = xv[k], w4 = wv[k];
                    acc += a.x * w4.x + a.y * w4.y + a.z * w4.z + a.w * w4.w;
                }
                const int row = r0 + r;
                if (c < 8)       d_fb[row * CF + c] = __float2bfloat16(acc);
                else if (c < 16) d_gb[row * CF + (c - 8)] = __float2bfloat16(acc);
                else             hs[(c - 16) * 33 + r] = acc;
            }
            __syncthreads();

            // transposed h store: ch = tid/2 (64 ch), 16 keys per thread
            {
                const int bb = r0 >> 12, n0 = r0 & (NTOK - 1);
                const int ch = tid >> 1, part = (tid & 1) * 16;
                __nv_bfloat16 v[16];
                #pragma unroll
                for (int j = 0; j < 16; j++) v[j] = __float2bfloat16(hs[ch * 33 + part + j]);
                uint4* dst = (uint4*)(d_htb + ((size_t)bb * CDIM + ch) * NTOK + n0 + part);
                dst[0] = *(const uint4*)(v);
                dst[1] = *(const uint4*)(v + 8);
            }
        }
    }

    // ================= device-wide barrier =================
    __threadfence();
    __syncthreads();
    if (tid == 0) {
        const unsigned int ticket = atomicAdd(&d_bar, 1u);
        const unsigned int target = ((ticket >> 8) + 1u) << 8;   // next multiple of 256
        unsigned int v;
        do {
            asm volatile("ld.acquire.gpu.u32 %0, [%1];" : "=r"(v) : "l"(&d_bar));
        } while (v < target);
    }
    __syncthreads();

    // ================= phase 2: flash attention (R8 core) =================
    __nv_bfloat16* fSb = (__nv_bfloat16*)smraw;             // stage s: s*512 elems
    __nv_bfloat16* hSb = (__nv_bfloat16*)(smraw + 4096);    // stage s: s*4608 elems

    const int warp = tid >> 5;
    const int lane = tid & 31;
    const int gid  = lane >> 2;
    const int tig  = lane & 3;
    const int mat  = lane >> 3;
    const int mrow = lane & 7;

    const int b    = blockIdx.y;
    const int q0   = blockIdx.x * QPC + warp * 16;
    const int row0 = b * NTOK + q0;

    const int f_off = (mat * 8 + mrow) * CF;
    const int h_off = ((mat >> 1) * 8 + mrow) * HP + (mat & 1) * 8;

    const uint32_t ga0 = *reinterpret_cast<const uint32_t*>(d_gb + (row0 + gid) * CF + tig * 2);
    const uint32_t ga1 = *reinterpret_cast<const uint32_t*>(d_gb + (row0 + 8 + gid) * CF + tig * 2);

    float O[8][4];
    #pragma unroll
    for (int n = 0; n < 8; n++)
        #pragma unroll
        for (int j = 0; j < 4; j++) O[n][j] = 0.0f;
    float l0 = 0.0f, l1 = 0.0f;
    const float zc[4] = {0.0f, 0.0f, 0.0f, 0.0f};

    auto load_tile = [&](int t) {
        const int buf = t & (STG - 1);
        if (tid < 64)
            cp16(&fSb[buf * 512 + tid * CF], d_fb + (size_t)(b * NTOK + t * KT + tid) * CF);
        const __nv_bfloat16* hsrc = d_htb + (size_t)b * CDIM * NTOK + t * KT;
        #pragma unroll
        for (int k2 = 0; k2 < 4; k2++) {
            const int i  = tid + k2 * 128;
            const int ch = i >> 3, ck = i & 7;
            cp16(&hSb[buf * 4608 + ch * HP + ck * 8], hsrc + (size_t)ch * NTOK + ck * 8);
        }
    };

    load_tile(0); CP_COMMIT();
    load_tile(1); CP_COMMIT();
    load_tile(2); CP_COMMIT();

    for (int t = 0; t < NTILE; t++) {
        CP_WAIT2();
        __syncthreads();
        if (t + 3 < NTILE) load_tile(t + 3);
        CP_COMMIT();

        const int buf = t & (STG - 1);

        // --- QK: S[16q x 64k] ---
        float S[8][4];
        {
            uint32_t fb[8];
            ldmat4(fb[0], fb[1], fb[2], fb[3], &fSb[buf * 512 + f_off]);
            ldmat4(fb[4], fb[5], fb[6], fb[7], &fSb[buf * 512 + f_off + 32 * CF]);
            #pragma unroll
            for (int n = 0; n < 8; n++) MMA1688(S[n], ga0, ga1, fb[n], zc);
        }

        // --- exp + row sums + pack P ---
        uint32_t P[8][2];
        #pragma unroll
        for (int n = 0; n < 8; n++) {
            const float e0 = __expf(S[n][0]);
            const float e1 = __expf(S[n][1]);
            const float e2 = __expf(S[n][2]);
            const float e3 = __expf(S[n][3]);
            l0 += e0 + e1;
            l1 += e2 + e3;
            CVT_BF16X2(P[n][0], e0, e1);
            CVT_BF16X2(P[n][1], e2, e3);
        }

        // --- PV: O += P @ H^T ---
        #pragma unroll
        for (int kk = 0; kk < 4; kk++) {
            const uint32_t a0 = P[2 * kk][0];
            const uint32_t a1 = P[2 * kk][1];
            const uint32_t a2 = P[2 * kk + 1][0];
            const uint32_t a3 = P[2 * kk + 1][1];
            #pragma unroll
            for (int np = 0; np < 4; np++) {
                uint32_t b0, b1, b2, b3;
                ldmat4(b0, b1, b2, b3, &hSb[buf * 4608 + h_off + np * 16 * HP + kk * 16]);
                MMA16816(O[2 * np],     a0, a1, a2, a3, b0, b1, O[2 * np]);
                MMA16816(O[2 * np + 1], a0, a1, a2, a3, b2, b3, O[2 * np + 1]);
            }
        }
    }

    l0 += __shfl_xor_sync(0xFFFFFFFF, l0, 1);
    l0 += __shfl_xor_sync(0xFFFFFFFF, l0, 2);
    l1 += __shfl_xor_sync(0xFFFFFFFF, l1, 1);
    l1 += __shfl_xor_sync(0xFFFFFFFF, l1, 2);

    const float gm   = gamma[0];
    const float inv0 = gm / l0;
    const float inv1 = gm / l1;

    const size_t base0 = (size_t)(row0 + gid) * CDIM;
    const size_t base1 = (size_t)(row0 + 8 + gid) * CDIM;
    #pragma unroll
    for (int n = 0; n < 8; n++) {
        const int ch = n * 8 + tig * 2;
        const float2 xv0 = *reinterpret_cast<const float2*>(x + base0 + ch);
        const float2 xv1 = *reinterpret_cast<const float2*>(x + base1 + ch);
        float2 o0, o1;
        o0.x = fmaf(inv0, O[n][0], xv0.x);
        o0.y = fmaf(inv0, O[n][1], xv0.y);
        o1.x = fmaf(inv1, O[n][2], xv1.x);
        o1.y = fmaf(inv1, O[n][3], xv1.y);
        *reinterpret_cast<float2*>(out + base0 + ch) = o0;
        *reinterpret_cast<float2*>(out + base1 + ch) = o1;
    }
}

// ---------------- launch ----------------
extern "C" void kernel_launch(void* const* d_in, const int* in_sizes, int n_in,
                              void* d_out, int out_size) {
    const float* x     = (const float*)d_in[0];
    const float* w_f   = (const float*)d_in[1];
    const float* b_f   = (const float*)d_in[2];
    const float* w_g   = (const float*)d_in[3];
    const float* b_g   = (const float*)d_in[4];
    const float* w_h   = (const float*)d_in[5];
    const float* b_h   = (const float*)d_in[6];
    const float* gamma = (const float*)d_in[7];
    float* out = (float*)d_out;

    fused_kernel<<<dim3(NTOK / QPC, BATCH), 128>>>(x, w_f, b_f, w_g, b_g,
                                                   w_h, b_h, gamma, out);
}